// round 11
// baseline (speedup 1.0000x reference)
#include <cuda_runtime.h>
#include <math.h>

#define NNODES 50000
#define NEDGES 800000
#define HID 128
#define NTYPES 4
#define YCOLS (NTYPES * HID)   /* 512 */
#define GCOLS (3 * HID)        /* 384 */

// ---------------- device scratch (no allocations allowed) ----------------
__device__ float g_Wcat[HID * YCOLS];                 // 128 x 512 concat of type_weights
__device__ float g_Y[(size_t)NNODES * YCOLS];         // h @ Wcat           (102.4 MB)
__device__ float g_msg[(size_t)NNODES * HID];         // aggregated messages (25.6 MB)
__device__ int   g_cnt[NNODES * NTYPES];              // per (node,type) in-degree
__device__ float g_S[(size_t)NNODES * GCOLS];         // messages @ gru_kernel + b0
__device__ float g_T[(size_t)NNODES * GCOLS];         // h @ gru_rec_kernel + b1
__device__ float g_H[(size_t)NNODES * HID];           // intermediate hidden state

// ---------------- prep: Wcat[k][t*128+j] = tw[t][k][j] ----------------
__global__ void prep_wcat(const float* __restrict__ tw) {
    int i = blockIdx.x * 256 + threadIdx.x;           // 65536 total
    int k = i >> 9;
    int c = i & 511;
    int t = c >> 7;
    int j = c & 127;
    g_Wcat[i] = tw[t * HID * HID + k * HID + j];
}

// ---------------- zero messages + counts ----------------
__global__ void zero_kernel() {
    int i = blockIdx.x * 256 + threadIdx.x;           // 1,600,000 float4s
    ((float4*)g_msg)[i] = make_float4(0.f, 0.f, 0.f, 0.f);
    if (i < NNODES) ((int4*)g_cnt)[i] = make_int4(0, 0, 0, 0);
}

// ---------------- generic SGEMM: C[M,N] = A[M,128] @ B[128,N] (+ bias row) ----------------
// 64x64 tile, 256 threads, 4x4 microtile, K split in two 64-chunks (smem <= 48KB).
__global__ __launch_bounds__(256) void sgemm128(
    const float* __restrict__ A, const float* __restrict__ B,
    float* __restrict__ C, int M, int N, const float* __restrict__ bias)
{
    __shared__ float As[64][68];   // [m][k], row stride 68 floats (16B aligned, conflict-free)
    __shared__ float Bs[64][68];   // [k][n]

    const int bm = blockIdx.y << 6;
    const int bn = blockIdx.x << 6;
    const int tid = threadIdx.x;
    const int tx = tid & 15, ty = tid >> 4;
    const int m0 = ty << 2, n0 = tx << 2;

    float acc[4][4];
#pragma unroll
    for (int i = 0; i < 4; i++)
#pragma unroll
        for (int j = 0; j < 4; j++) acc[i][j] = 0.f;

    for (int kk = 0; kk < HID; kk += 64) {
        // load A tile: 64 rows x 64 ks  (coalesced float4, conflict-free smem stores)
#pragma unroll
        for (int q = tid; q < 1024; q += 256) {
            int r = q >> 4, kq = (q & 15) << 2;
            float4 a = make_float4(0.f, 0.f, 0.f, 0.f);
            int row = bm + r;
            if (row < M) a = *(const float4*)(A + (size_t)row * HID + kk + kq);
            *(float4*)&As[r][kq] = a;
        }
        // load B tile: 64 ks x 64 cols
#pragma unroll
        for (int q = tid; q < 1024; q += 256) {
            int k = q >> 4, nq = (q & 15) << 2;
            float4 b = *(const float4*)(B + (size_t)(kk + k) * N + bn + nq);
            *(float4*)&Bs[k][nq] = b;
        }
        __syncthreads();

#pragma unroll 8
        for (int k = 0; k < 64; k++) {
            float4 b = *(const float4*)&Bs[k][n0];
            float a0 = As[m0 + 0][k];
            float a1 = As[m0 + 1][k];
            float a2 = As[m0 + 2][k];
            float a3 = As[m0 + 3][k];
            acc[0][0] = fmaf(a0, b.x, acc[0][0]);
            acc[0][1] = fmaf(a0, b.y, acc[0][1]);
            acc[0][2] = fmaf(a0, b.z, acc[0][2]);
            acc[0][3] = fmaf(a0, b.w, acc[0][3]);
            acc[1][0] = fmaf(a1, b.x, acc[1][0]);
            acc[1][1] = fmaf(a1, b.y, acc[1][1]);
            acc[1][2] = fmaf(a1, b.z, acc[1][2]);
            acc[1][3] = fmaf(a1, b.w, acc[1][3]);
            acc[2][0] = fmaf(a2, b.x, acc[2][0]);
            acc[2][1] = fmaf(a2, b.y, acc[2][1]);
            acc[2][2] = fmaf(a2, b.z, acc[2][2]);
            acc[2][3] = fmaf(a2, b.w, acc[2][3]);
            acc[3][0] = fmaf(a3, b.x, acc[3][0]);
            acc[3][1] = fmaf(a3, b.y, acc[3][1]);
            acc[3][2] = fmaf(a3, b.z, acc[3][2]);
            acc[3][3] = fmaf(a3, b.w, acc[3][3]);
        }
        __syncthreads();
    }

    float b0 = 0.f, b1 = 0.f, b2 = 0.f, b3 = 0.f;
    if (bias) {
        b0 = bias[bn + n0 + 0];
        b1 = bias[bn + n0 + 1];
        b2 = bias[bn + n0 + 2];
        b3 = bias[bn + n0 + 3];
    }
#pragma unroll
    for (int i = 0; i < 4; i++) {
        int row = bm + m0 + i;
        if (row < M) {
            float4 o = make_float4(acc[i][0] + b0, acc[i][1] + b1,
                                   acc[i][2] + b2, acc[i][3] + b3);
            *(float4*)(C + (size_t)row * N + bn + n0) = o;
        }
    }
}

// ---------------- scatter: messages[tgt] += Y[src][etype block]; counts++ ----------------
// One warp per edge. Atomic destination is 25.6MB -> L2-resident.
__global__ __launch_bounds__(256) void scatter_kernel(const int* __restrict__ edges) {
    int gw = (blockIdx.x * 256 + threadIdx.x) >> 5;
    int lane = threadIdx.x & 31;
    if (gw >= NEDGES) return;
    int et  = __ldg(edges + gw * 3 + 0);
    int src = __ldg(edges + gw * 3 + 1);
    int tgt = __ldg(edges + gw * 3 + 2);
    float4 v = *(const float4*)(g_Y + (size_t)src * YCOLS + et * HID + (lane << 2));
    float* d = g_msg + (size_t)tgt * HID + (lane << 2);
    atomicAdd(d + 0, v.x);
    atomicAdd(d + 1, v.y);
    atomicAdd(d + 2, v.z);
    atomicAdd(d + 3, v.w);
    if (lane == 0) atomicAdd(g_cnt + tgt * NTYPES + et, 1);
}

// ---------------- bias: messages += counts @ type_biases ----------------
__global__ void bias_kernel(const float* __restrict__ tb) {
    int i = blockIdx.x * 256 + threadIdx.x;           // exactly NNODES*HID
    int v = i >> 7, j = i & 127;
    const int* c = g_cnt + v * 4;
    float add = (float)c[0] * tb[j] + (float)c[1] * tb[HID + j]
              + (float)c[2] * tb[2 * HID + j] + (float)c[3] * tb[3 * HID + j];
    g_msg[i] += add;
}

// ---------------- GRU elementwise ----------------
__global__ void gru_kernel(const float* __restrict__ h_in, float* __restrict__ h_out) {
    int i = blockIdx.x * 256 + threadIdx.x;           // exactly NNODES*HID
    int n = i >> 7, j = i & 127;
    size_t b = (size_t)n * GCOLS;
    float xz = g_S[b + j], xr = g_S[b + HID + j], xh = g_S[b + 2 * HID + j];
    float rz = g_T[b + j], rr = g_T[b + HID + j], rh = g_T[b + 2 * HID + j];
    float z  = 1.f / (1.f + expf(-(xz + rz)));
    float r  = 1.f / (1.f + expf(-(xr + rr)));
    float hh = tanhf(xh + r * rh);
    float h  = h_in[i];
    h_out[i] = z * h + (1.f - z) * hh;
}

// ---------------- launch ----------------
extern "C" void kernel_launch(void* const* d_in, const int* in_sizes, int n_in,
                              void* d_out, int out_size) {
    const float* states = (const float*)d_in[0];   // (50000,128)
    const int*   edges  = (const int*)d_in[1];     // (800000,3) [etype,src,tgt]
    const float* tw     = (const float*)d_in[2];   // (4,128,128)
    const float* tb     = (const float*)d_in[3];   // (4,128)
    const float* gk     = (const float*)d_in[4];   // (128,384)
    const float* grk    = (const float*)d_in[5];   // (128,384)
    const float* gb     = (const float*)d_in[6];   // (2,384)
    float* out = (float*)d_out;

    float *pWcat, *pY, *pMsg, *pS, *pT, *pH;
    cudaGetSymbolAddress((void**)&pWcat, g_Wcat);
    cudaGetSymbolAddress((void**)&pY,    g_Y);
    cudaGetSymbolAddress((void**)&pMsg,  g_msg);
    cudaGetSymbolAddress((void**)&pS,    g_S);
    cudaGetSymbolAddress((void**)&pT,    g_T);
    cudaGetSymbolAddress((void**)&pH,    g_H);

    prep_wcat<<<256, 256>>>(tw);

    const float* h_in = states;
    float* h_out = pH;
    for (int step = 0; step < 2; step++) {
        zero_kernel<<<6250, 256>>>();
        // Y = h @ Wcat   (M=50000, N=512, K=128)
        sgemm128<<<dim3(8, 782), 256>>>(h_in, pWcat, pY, NNODES, YCOLS, nullptr);
        // messages = segment_sum(Y[src, etype-block]) over tgt
        scatter_kernel<<<100000, 256>>>(edges);
        // messages += counts @ type_biases
        bias_kernel<<<25000, 256>>>(tb);
        // S = messages @ gru_kernel + gb[0];  T = h @ gru_rec_kernel + gb[1]
        sgemm128<<<dim3(6, 782), 256>>>(pMsg, gk,  pS, NNODES, GCOLS, gb);
        sgemm128<<<dim3(6, 782), 256>>>(h_in, grk, pT, NNODES, GCOLS, gb + GCOLS);
        // h = GRU(messages, h)
        gru_kernel<<<25000, 256>>>(h_in, h_out);

        h_in = pH;
        h_out = out;   // step 1 writes final output
    }
}

// round 12
// speedup vs baseline: 1.4254x; 1.4254x over previous
#include <cuda_runtime.h>
#include <math.h>

#define NNODES 50000
#define NEDGES 800000
#define HID 128
#define NTYPES 4
#define YCOLS (NTYPES * HID)   /* 512 */
#define GCOLS (3 * HID)        /* 384 */

// ---------------- device scratch (no allocations allowed) ----------------
__device__ float g_Wcat[HID * YCOLS];                 // 128 x 512 concat of type_weights
__device__ float g_Y[(size_t)NNODES * YCOLS];         // h @ Wcat           (102.4 MB)
__device__ float g_msg[(size_t)NNODES * HID];         // aggregated messages (25.6 MB)
__device__ int   g_cnt[NNODES * NTYPES];              // per (node,type) in-degree
__device__ float g_S[(size_t)NNODES * GCOLS];         // messages @ gru_kernel + b0
__device__ float g_T[(size_t)NNODES * GCOLS];         // h @ gru_rec_kernel + b1
__device__ float g_H[(size_t)NNODES * HID];           // intermediate hidden state

// ---- f32x2 packed-FMA helpers (sm_10x dual-fp32 pipe; PTX-only) ----
#define FMA2(d, a, b, c) \
    asm("fma.rn.f32x2 %0, %1, %2, %3;" : "=l"(d) : "l"(a), "l"(b), "l"(c))
#define DUP2(d, f) \
    asm("mov.b64 %0, {%1, %1};" : "=l"(d) : "f"(f))
#define UNPACK2(lo, hi, v) \
    asm("mov.b64 {%0, %1}, %2;" : "=f"(lo), "=f"(hi) : "l"(v))

// ---------------- prep: Wcat[k][t*128+j] = tw[t][k][j] ----------------
__global__ void prep_wcat(const float* __restrict__ tw) {
    int i = blockIdx.x * 256 + threadIdx.x;           // 65536 total
    int k = i >> 9;
    int c = i & 511;
    int t = c >> 7;
    int j = c & 127;
    g_Wcat[i] = tw[t * HID * HID + k * HID + j];
}

// ---------------- zero messages + counts ----------------
__global__ void zero_kernel() {
    int i = blockIdx.x * 256 + threadIdx.x;           // 1,600,000 float4s
    ((float4*)g_msg)[i] = make_float4(0.f, 0.f, 0.f, 0.f);
    if (i < NNODES) ((int4*)g_cnt)[i] = make_int4(0, 0, 0, 0);
}

// ---------------- SGEMM: C[M,N] = A[M,128] @ B[128,N] (+ bias row) ----------------
// 128x64 block tile, 256 threads, 8x4 microtile, K in 32-chunks.
// A tile stored TRANSPOSED [k][m] so an LDS64 gives a packed m-pair for fma.rn.f32x2.
// Inner loop per k: 4xLDS64(a-pairs) + 1xLDS128(b) + 4x mov.b64 dup + 16x FFMA2
//   -> 25 issues vs 32 fma-pipe cycles: FMA2-bound (2x scalar-FFMA throughput).
__global__ __launch_bounds__(256) void sgemm128(
    const float* __restrict__ A, const float* __restrict__ B,
    float* __restrict__ C, int M, int N, const float* __restrict__ bias)
{
    __shared__ float As[32][130];   // [k][m], stride 130 (even -> 8B-aligned LDS64)
    __shared__ float Bs[32][68];    // [k][n], 16B-aligned rows

    const int bm = blockIdx.y << 7;   // 128 rows
    const int bn = blockIdx.x << 6;   // 64 cols
    const int tid = threadIdx.x;
    const int tx = tid & 15, ty = tid >> 4;
    const int m0 = ty << 3;           // 8 rows / thread
    const int n0 = tx << 2;           // 4 cols / thread

    unsigned long long acc[4][4];     // [m-pair][n]  (each holds rows m0+2p, m0+2p+1)
#pragma unroll
    for (int p = 0; p < 4; p++)
#pragma unroll
        for (int j = 0; j < 4; j++) acc[p][j] = 0ull;

    for (int kk = 0; kk < HID; kk += 32) {
        // A tile: 128 rows x 32 ks, loaded as float4 along k, stored transposed.
#pragma unroll
        for (int it = 0; it < 4; it++) {
            int q = tid + (it << 8);
            int r = q >> 3;                 // 0..127 (row in tile)
            int kq = (q & 7) << 2;          // 0..28
            float4 a = make_float4(0.f, 0.f, 0.f, 0.f);
            int row = bm + r;
            if (row < M) a = *(const float4*)(A + (size_t)row * HID + kk + kq);
            As[kq + 0][r] = a.x;
            As[kq + 1][r] = a.y;
            As[kq + 2][r] = a.z;
            As[kq + 3][r] = a.w;
        }
        // B tile: 32 ks x 64 cols
#pragma unroll
        for (int it = 0; it < 2; it++) {
            int q = tid + (it << 8);
            int k = q >> 4, nq = (q & 15) << 2;
            *(float4*)&Bs[k][nq] =
                *(const float4*)(B + (size_t)(kk + k) * N + bn + nq);
        }
        __syncthreads();

#pragma unroll
        for (int k = 0; k < 32; k++) {
            float4 b = *(const float4*)&Bs[k][n0];
            unsigned long long bd0, bd1, bd2, bd3;
            DUP2(bd0, b.x); DUP2(bd1, b.y); DUP2(bd2, b.z); DUP2(bd3, b.w);
            unsigned long long a0 = *(const unsigned long long*)&As[k][m0 + 0];
            unsigned long long a1 = *(const unsigned long long*)&As[k][m0 + 2];
            unsigned long long a2 = *(const unsigned long long*)&As[k][m0 + 4];
            unsigned long long a3 = *(const unsigned long long*)&As[k][m0 + 6];
            FMA2(acc[0][0], a0, bd0, acc[0][0]);
            FMA2(acc[0][1], a0, bd1, acc[0][1]);
            FMA2(acc[0][2], a0, bd2, acc[0][2]);
            FMA2(acc[0][3], a0, bd3, acc[0][3]);
            FMA2(acc[1][0], a1, bd0, acc[1][0]);
            FMA2(acc[1][1], a1, bd1, acc[1][1]);
            FMA2(acc[1][2], a1, bd2, acc[1][2]);
            FMA2(acc[1][3], a1, bd3, acc[1][3]);
            FMA2(acc[2][0], a2, bd0, acc[2][0]);
            FMA2(acc[2][1], a2, bd1, acc[2][1]);
            FMA2(acc[2][2], a2, bd2, acc[2][2]);
            FMA2(acc[2][3], a2, bd3, acc[2][3]);
            FMA2(acc[3][0], a3, bd0, acc[3][0]);
            FMA2(acc[3][1], a3, bd1, acc[3][1]);
            FMA2(acc[3][2], a3, bd2, acc[3][2]);
            FMA2(acc[3][3], a3, bd3, acc[3][3]);
        }
        __syncthreads();
    }

    float b0 = 0.f, b1 = 0.f, b2 = 0.f, b3 = 0.f;
    if (bias) {
        b0 = bias[bn + n0 + 0];
        b1 = bias[bn + n0 + 1];
        b2 = bias[bn + n0 + 2];
        b3 = bias[bn + n0 + 3];
    }
#pragma unroll
    for (int p = 0; p < 4; p++) {
        float lo0, hi0, lo1, hi1, lo2, hi2, lo3, hi3;
        UNPACK2(lo0, hi0, acc[p][0]);
        UNPACK2(lo1, hi1, acc[p][1]);
        UNPACK2(lo2, hi2, acc[p][2]);
        UNPACK2(lo3, hi3, acc[p][3]);
        int r0 = bm + m0 + (p << 1);
        if (r0 < M)
            *(float4*)(C + (size_t)r0 * N + bn + n0) =
                make_float4(lo0 + b0, lo1 + b1, lo2 + b2, lo3 + b3);
        if (r0 + 1 < M)
            *(float4*)(C + (size_t)(r0 + 1) * N + bn + n0) =
                make_float4(hi0 + b0, hi1 + b1, hi2 + b2, hi3 + b3);
    }
}

// ---------------- scatter: messages[tgt] += Y[src][etype block]; counts++ ----------------
// One warp per edge; one red.global.add.v4.f32 per lane (4x fewer RED wavefronts).
__global__ __launch_bounds__(256) void scatter_kernel(const int* __restrict__ edges) {
    int gw = (blockIdx.x * 256 + threadIdx.x) >> 5;
    int lane = threadIdx.x & 31;
    if (gw >= NEDGES) return;
    int et  = __ldg(edges + gw * 3 + 0);
    int src = __ldg(edges + gw * 3 + 1);
    int tgt = __ldg(edges + gw * 3 + 2);
    float4 v = *(const float4*)(g_Y + (size_t)src * YCOLS + et * HID + (lane << 2));
    float* d = g_msg + (size_t)tgt * HID + (lane << 2);
    asm volatile("red.global.add.v4.f32 [%0], {%1, %2, %3, %4};"
                 :: "l"(d), "f"(v.x), "f"(v.y), "f"(v.z), "f"(v.w)
                 : "memory");
    if (lane == 0) atomicAdd(g_cnt + tgt * NTYPES + et, 1);
}

// ---------------- bias: messages += counts @ type_biases ----------------
__global__ void bias_kernel(const float* __restrict__ tb) {
    int i = blockIdx.x * 256 + threadIdx.x;           // exactly NNODES*HID
    int v = i >> 7, j = i & 127;
    const int* c = g_cnt + v * 4;
    float add = (float)c[0] * tb[j] + (float)c[1] * tb[HID + j]
              + (float)c[2] * tb[2 * HID + j] + (float)c[3] * tb[3 * HID + j];
    g_msg[i] += add;
}

// ---------------- GRU elementwise ----------------
__global__ void gru_kernel(const float* __restrict__ h_in, float* __restrict__ h_out) {
    int i = blockIdx.x * 256 + threadIdx.x;           // exactly NNODES*HID
    int n = i >> 7, j = i & 127;
    size_t b = (size_t)n * GCOLS;
    float xz = g_S[b + j], xr = g_S[b + HID + j], xh = g_S[b + 2 * HID + j];
    float rz = g_T[b + j], rr = g_T[b + HID + j], rh = g_T[b + 2 * HID + j];
    float z  = 1.f / (1.f + expf(-(xz + rz)));
    float r  = 1.f / (1.f + expf(-(xr + rr)));
    float hh = tanhf(xh + r * rh);
    float h  = h_in[i];
    h_out[i] = z * h + (1.f - z) * hh;
}

// ---------------- launch ----------------
extern "C" void kernel_launch(void* const* d_in, const int* in_sizes, int n_in,
                              void* d_out, int out_size) {
    const float* states = (const float*)d_in[0];   // (50000,128)
    const int*   edges  = (const int*)d_in[1];     // (800000,3) [etype,src,tgt]
    const float* tw     = (const float*)d_in[2];   // (4,128,128)
    const float* tb     = (const float*)d_in[3];   // (4,128)
    const float* gk     = (const float*)d_in[4];   // (128,384)
    const float* grk    = (const float*)d_in[5];   // (128,384)
    const float* gb     = (const float*)d_in[6];   // (2,384)
    float* out = (float*)d_out;

    float *pWcat, *pY, *pMsg, *pS, *pT, *pH;
    cudaGetSymbolAddress((void**)&pWcat, g_Wcat);
    cudaGetSymbolAddress((void**)&pY,    g_Y);
    cudaGetSymbolAddress((void**)&pMsg,  g_msg);
    cudaGetSymbolAddress((void**)&pS,    g_S);
    cudaGetSymbolAddress((void**)&pT,    g_T);
    cudaGetSymbolAddress((void**)&pH,    g_H);

    prep_wcat<<<256, 256>>>(tw);

    const int mblocks = (NNODES + 127) / 128;   // 391

    const float* h_in = states;
    float* h_out = pH;
    for (int step = 0; step < 2; step++) {
        zero_kernel<<<6250, 256>>>();
        // Y = h @ Wcat   (M=50000, N=512, K=128)
        sgemm128<<<dim3(8, mblocks), 256>>>(h_in, pWcat, pY, NNODES, YCOLS, nullptr);
        // messages = segment_sum(Y[src, etype-block]) over tgt
        scatter_kernel<<<100000, 256>>>(edges);
        // messages += counts @ type_biases
        bias_kernel<<<25000, 256>>>(tb);
        // S = messages @ gru_kernel + gb[0];  T = h @ gru_rec_kernel + gb[1]
        sgemm128<<<dim3(6, mblocks), 256>>>(pMsg, gk,  pS, NNODES, GCOLS, gb);
        sgemm128<<<dim3(6, mblocks), 256>>>(h_in, grk, pT, NNODES, GCOLS, gb + GCOLS);
        // h = GRU(messages, h)
        gru_kernel<<<25000, 256>>>(h_in, h_out);

        h_in = pH;
        h_out = out;   // step 1 writes final output
    }
}